// round 1
// baseline (speedup 1.0000x reference)
#include <cuda_runtime.h>
#include <math.h>

// Problem constants
#define D     1024
#define H_    16
#define HD    64
#define FF    4096
#define NB    2
#define LQ    2048
#define MROWS (NB * LQ)   // 4096
#define EPS   1e-5f

// ---------------------------------------------------------------------------
// Scratch (device globals — no allocation allowed)
// ---------------------------------------------------------------------------
__device__ float g_qkv [MROWS * 3 * D];  // 48 MB
__device__ float g_attn[MROWS * D];      // 16 MB
__device__ float g_proj[MROWS * D];      // 16 MB
__device__ float g_h   [MROWS * D];      // 16 MB
__device__ float g_ff1 [MROWS * FF];     // 64 MB
__device__ float g_ff2 [MROWS * D];      // 16 MB

__device__ __forceinline__ float* scratch(int id) {
    switch (id) {
        case 0:  return g_qkv;
        case 1:  return g_attn;
        case 2:  return g_proj;
        case 3:  return g_h;
        case 4:  return g_ff1;
        default: return g_ff2;
    }
}

// ---------------------------------------------------------------------------
// SGEMM: C[M,N] = A[M,K] @ B[K,N] + bias[N]  (optional ReLU)
// A row-major, B row-major. M%128==0, N%128==0, K%8==0 (guaranteed here).
// BM=BN=128, BK=8, 256 threads, 8x8 microtile per thread.
// ---------------------------------------------------------------------------
__global__ __launch_bounds__(256)
void sgemm_bias(const float* __restrict__ Aext, int Aid,
                const float* __restrict__ B,
                const float* __restrict__ bias,
                float* __restrict__ Cext, int Cid,
                int M, int N, int K, int relu)
{
    const float* A = Aext ? Aext : scratch(Aid);
    float*       C = Cext ? Cext : scratch(Cid);

    __shared__ float As[8][128];
    __shared__ float Bs[8][128];

    const int tid = threadIdx.x;
    const int tx  = tid & 15;          // 0..15  (N direction)
    const int ty  = tid >> 4;          // 0..15  (M direction)
    const int m0  = blockIdx.y * 128;
    const int n0  = blockIdx.x * 128;

    // A loader coords: each thread loads one float4 (row, 4 k-cols)
    const int arow  = tid >> 1;          // 0..127
    const int acol4 = (tid & 1) * 4;     // 0 or 4
    // B loader coords: each thread loads one float4 (k-row, 4 n-cols)
    const int brow  = tid >> 5;          // 0..7
    const int bcol4 = (tid & 31) * 4;    // 0..124

    float acc[8][8];
    #pragma unroll
    for (int i = 0; i < 8; i++)
        #pragma unroll
        for (int j = 0; j < 8; j++) acc[i][j] = 0.f;

    for (int k0 = 0; k0 < K; k0 += 8) {
        float4 av = *(const float4*)&A[(size_t)(m0 + arow) * K + k0 + acol4];
        As[acol4 + 0][arow] = av.x;
        As[acol4 + 1][arow] = av.y;
        As[acol4 + 2][arow] = av.z;
        As[acol4 + 3][arow] = av.w;
        float4 bv = *(const float4*)&B[(size_t)(k0 + brow) * N + n0 + bcol4];
        *(float4*)&Bs[brow][bcol4] = bv;
        __syncthreads();

        #pragma unroll
        for (int kk = 0; kk < 8; kk++) {
            float a[8], b[8];
            #pragma unroll
            for (int i = 0; i < 8; i++) a[i] = As[kk][ty * 8 + i];
            #pragma unroll
            for (int j = 0; j < 8; j++) b[j] = Bs[kk][tx * 8 + j];
            #pragma unroll
            for (int i = 0; i < 8; i++)
                #pragma unroll
                for (int j = 0; j < 8; j++)
                    acc[i][j] += a[i] * b[j];
        }
        __syncthreads();
    }

    #pragma unroll
    for (int i = 0; i < 8; i++) {
        int m = m0 + ty * 8 + i;
        #pragma unroll
        for (int j = 0; j < 8; j++) {
            int n = n0 + tx * 8 + j;
            float v = acc[i][j] + bias[n];
            if (relu) v = fmaxf(v, 0.f);
            C[(size_t)m * N + n] = v;
        }
    }
}

// ---------------------------------------------------------------------------
// Flash attention (fp32). Grid: (L/128, H, NB). Block: 128 threads.
// Each thread owns one q-row: q (64 regs), acc (64 regs), online softmax
// with two passes per 64-key tile (pass1 tile max, pass2 exp+accumulate).
// K/V tile reads from SMEM are uniform across threads -> broadcast, free.
// ---------------------------------------------------------------------------
__global__ __launch_bounds__(128)
void attn_kernel()
{
    const int n  = blockIdx.z;
    const int h  = blockIdx.y;
    const int q0 = blockIdx.x * 128;
    const int tid = threadIdx.x;
    const int row = n * LQ + q0 + tid;          // global token row

    __shared__ float Ks[64][64];
    __shared__ float Vs[64][64];

    const float scale = 0.125f;                 // 1/sqrt(64)
    float qreg[HD];
    {
        const float* qp = &g_qkv[(size_t)row * (3 * D) + h * HD];
        #pragma unroll
        for (int d = 0; d < HD; d++) qreg[d] = qp[d] * scale;
    }

    float m = -1e30f, l = 0.f;
    float acc[HD];
    #pragma unroll
    for (int d = 0; d < HD; d++) acc[d] = 0.f;

    for (int kt = 0; kt < LQ / 64; kt++) {
        // load K/V tile: 64 rows x 64 cols, 1024 float4s total across both
        for (int i = tid; i < 64 * 16; i += 128) {
            int r  = i >> 4;
            int c4 = (i & 15) * 4;
            size_t base = (size_t)(n * LQ + kt * 64 + r) * (3 * D) + h * HD + c4;
            *(float4*)&Ks[r][c4] = *(const float4*)&g_qkv[base + D];
            *(float4*)&Vs[r][c4] = *(const float4*)&g_qkv[base + 2 * D];
        }
        __syncthreads();

        // pass 1: tile max
        float tmax = -1e30f;
        #pragma unroll 4
        for (int j = 0; j < 64; j++) {
            float s = 0.f;
            #pragma unroll
            for (int d = 0; d < HD; d++) s += qreg[d] * Ks[j][d];
            tmax = fmaxf(tmax, s);
        }
        float mnew = fmaxf(m, tmax);
        float corr = __expf(m - mnew);
        l *= corr;
        #pragma unroll
        for (int d = 0; d < HD; d++) acc[d] *= corr;

        // pass 2: exp + accumulate P@V
        #pragma unroll 2
        for (int j = 0; j < 64; j++) {
            float s = 0.f;
            #pragma unroll
            for (int d = 0; d < HD; d++) s += qreg[d] * Ks[j][d];
            float p = __expf(s - mnew);
            l += p;
            #pragma unroll
            for (int d = 0; d < HD; d++) acc[d] += p * Vs[j][d];
        }
        m = mnew;
        __syncthreads();
    }

    const float inv = 1.f / l;
    float* op = &g_attn[(size_t)row * D + h * HD];
    #pragma unroll
    for (int d = 0; d < HD; d++) op[d] = acc[d] * inv;
}

// ---------------------------------------------------------------------------
// Residual add + LayerNorm: out = LN(a + b) * gamma + beta
// One block (256 threads) per row of 1024.
// ---------------------------------------------------------------------------
__global__ __launch_bounds__(256)
void add_ln_kernel(const float* __restrict__ aext, int aid,
                   const float* __restrict__ bext, int bid,
                   const float* __restrict__ gamma,
                   const float* __restrict__ beta,
                   float* __restrict__ outext, int outid)
{
    const float* a = aext ? aext : scratch(aid);
    const float* b = bext ? bext : scratch(bid);
    float*       o = outext ? outext : scratch(outid);

    const int row = blockIdx.x;
    const int tid = threadIdx.x;
    const size_t base = (size_t)row * D;

    float v[4];
    float s = 0.f, s2 = 0.f;
    #pragma unroll
    for (int i = 0; i < 4; i++) {
        int col = tid + i * 256;
        float x = a[base + col] + b[base + col];
        v[i] = x;
        s  += x;
        s2 += x * x;
    }

    // warp reduce
    #pragma unroll
    for (int off = 16; off; off >>= 1) {
        s  += __shfl_xor_sync(0xFFFFFFFFu, s,  off);
        s2 += __shfl_xor_sync(0xFFFFFFFFu, s2, off);
    }
    __shared__ float rs[8], rs2[8];
    const int warp = tid >> 5, lane = tid & 31;
    if (lane == 0) { rs[warp] = s; rs2[warp] = s2; }
    __syncthreads();
    float ts = 0.f, ts2 = 0.f;
    #pragma unroll
    for (int w = 0; w < 8; w++) { ts += rs[w]; ts2 += rs2[w]; }

    const float mu  = ts * (1.f / D);
    const float var = ts2 * (1.f / D) - mu * mu;
    const float inv = rsqrtf(var + EPS);

    #pragma unroll
    for (int i = 0; i < 4; i++) {
        int col = tid + i * 256;
        o[base + col] = (v[i] - mu) * inv * gamma[col] + beta[col];
    }
}

// ---------------------------------------------------------------------------
// Launch
// ---------------------------------------------------------------------------
extern "C" void kernel_launch(void* const* d_in, const int* in_sizes, int n_in,
                              void* d_out, int out_size)
{
    const float* x     = (const float*)d_in[0];
    const float* w_qkv = (const float*)d_in[1];
    const float* b_qkv = (const float*)d_in[2];
    const float* w_o   = (const float*)d_in[3];
    const float* b_o   = (const float*)d_in[4];
    const float* g1    = (const float*)d_in[5];
    const float* be1   = (const float*)d_in[6];
    const float* w1    = (const float*)d_in[7];
    const float* b1    = (const float*)d_in[8];
    const float* w2    = (const float*)d_in[9];
    const float* b2    = (const float*)d_in[10];
    const float* g2    = (const float*)d_in[11];
    const float* be2   = (const float*)d_in[12];
    float* out = (float*)d_out;

    // 1. QKV: [4096,1024] @ [1024,3072] -> g_qkv (id 0)
    sgemm_bias<<<dim3(3 * D / 128, MROWS / 128), 256>>>(
        x, -1, w_qkv, b_qkv, nullptr, 0, MROWS, 3 * D, D, 0);

    // 2. attention -> g_attn (id 1)
    attn_kernel<<<dim3(LQ / 128, H_, NB), 128>>>();

    // 3. proj: g_attn @ w_o + b_o -> g_proj (id 2)
    sgemm_bias<<<dim3(D / 128, MROWS / 128), 256>>>(
        nullptr, 1, w_o, b_o, nullptr, 2, MROWS, D, D, 0);

    // 4. h = LN(proj + x) -> g_h (id 3)
    add_ln_kernel<<<MROWS, 256>>>(nullptr, 2, x, -1, g1, be1, nullptr, 3);

    // 5. FF1: relu(g_h @ w1 + b1) -> g_ff1 (id 4)
    sgemm_bias<<<dim3(FF / 128, MROWS / 128), 256>>>(
        nullptr, 3, w1, b1, nullptr, 4, MROWS, FF, D, 1);

    // 6. FF2: g_ff1 @ w2 + b2 -> g_ff2 (id 5)
    sgemm_bias<<<dim3(D / 128, MROWS / 128), 256>>>(
        nullptr, 4, w2, b2, nullptr, 5, MROWS, D, FF, 0);

    // 7. out = LN(g_h + g_ff2)
    add_ln_kernel<<<MROWS, 256>>>(nullptr, 3, nullptr, 5, g2, be2, out, -1);
}

// round 3
// speedup vs baseline: 1.8341x; 1.8341x over previous
#include <cuda_runtime.h>
#include <math.h>
#include <stdint.h>

// Problem constants
#define D     1024
#define H_    16
#define HD    64
#define FF    4096
#define NB    2
#define LQ    2048
#define MROWS (NB * LQ)   // 4096
#define EPS   1e-5f

// ---------------------------------------------------------------------------
// Scratch (device globals — no allocation allowed)
// ---------------------------------------------------------------------------
__device__ float g_qkv  [MROWS * 3 * D];
__device__ float g_attn [MROWS * D];
__device__ float g_proj [MROWS * D];
__device__ float g_h    [MROWS * D];
__device__ float g_ff1  [MROWS * FF];
__device__ float g_ff2  [MROWS * D];
__device__ float g_wqkvT[3 * D * D];   // [3072,1024]
__device__ float g_woT  [D * D];       // [1024,1024]
__device__ float g_w1T  [FF * D];      // [4096,1024]
__device__ float g_w2T  [D * FF];      // [1024,4096]

__device__ __forceinline__ float* scratch(int id) {
    switch (id) {
        case 0:  return g_qkv;
        case 1:  return g_attn;
        case 2:  return g_proj;
        case 3:  return g_h;
        case 4:  return g_ff1;
        case 5:  return g_ff2;
        case 6:  return g_wqkvT;
        case 7:  return g_woT;
        case 8:  return g_w1T;
        default: return g_w2T;
    }
}

// ---------------------------------------------------------------------------
// tf32 helpers (mma.sync path — works on base sm_103 target)
// ---------------------------------------------------------------------------
__device__ __forceinline__ uint32_t f2tf32(float x) {
    uint32_t r;
    asm("cvt.rna.tf32.f32 %0, %1;" : "=r"(r) : "f"(x));
    return r;
}

__device__ __forceinline__ void mma_tf32(float* c, const uint32_t* a, const uint32_t* b) {
    asm volatile(
        "mma.sync.aligned.m16n8k8.row.col.f32.tf32.tf32.f32 "
        "{%0,%1,%2,%3}, {%4,%5,%6,%7}, {%8,%9}, {%0,%1,%2,%3};"
        : "+f"(c[0]), "+f"(c[1]), "+f"(c[2]), "+f"(c[3])
        : "r"(a[0]), "r"(a[1]), "r"(a[2]), "r"(a[3]),
          "r"(b[0]), "r"(b[1]));
}

// ---------------------------------------------------------------------------
// Weight transpose: dst[c][r] = src[r][c], dst is scratch(dstId) [C,R]
// ---------------------------------------------------------------------------
__global__ __launch_bounds__(256)
void transpose_k(const float* __restrict__ src, int dstId, int R, int C)
{
    __shared__ float t[32][33];
    float* dst = scratch(dstId);
    const int bx = blockIdx.x * 32;
    const int by = blockIdx.y * 32;
    const int tx = threadIdx.x & 31;
    const int ty = threadIdx.x >> 5;
    #pragma unroll
    for (int i = 0; i < 32; i += 8)
        t[ty + i][tx] = src[(size_t)(by + ty + i) * C + bx + tx];
    __syncthreads();
    #pragma unroll
    for (int i = 0; i < 32; i += 8)
        dst[(size_t)(bx + ty + i) * R + by + tx] = t[tx][ty + i];
}

// ---------------------------------------------------------------------------
// TF32 tensor-core GEMM: C[M,N] = A[M,K] @ Bt[N,K]^T + bias (opt ReLU)
// Tile 128x128, BK=16, 256 threads (8 warps, 2x4 of 64x32 warp tiles).
// Permuted smem layout: k-group of 8 stored as [k0,k4,k1,k5,k2,k6,k3,k7]
// so each mma fragment load is one conflict-free lds.64 (row stride 24 words).
// ---------------------------------------------------------------------------
#define AS_STRIDE 24

__global__ __launch_bounds__(256)
void gemm_tf32(const float* __restrict__ Aext, int Aid, int Bid,
               const float* __restrict__ bias,
               float* __restrict__ Cext, int Cid,
               int M, int N, int K, int relu)
{
    __shared__ uint32_t As[128 * AS_STRIDE];
    __shared__ uint32_t Bs[128 * AS_STRIDE];

    const float* A  = Aext ? Aext : scratch(Aid);
    const float* Bt = scratch(Bid);                 // [N,K] K-major
    float*       C  = Cext ? Cext : scratch(Cid);

    const int tid   = threadIdx.x;
    const int wid   = tid >> 5;
    const int lane  = tid & 31;
    const int gid   = lane >> 2;      // 0..7
    const int tig   = lane & 3;       // 0..3
    const int warpM = (wid & 1) * 64;
    const int warpN = (wid >> 1) * 32;
    const int m0    = blockIdx.y * 128;
    const int n0    = blockIdx.x * 128;

    // loader coords: 256 threads, each loads 2 float4 from A and 2 from B per iter
    const int lr  = tid >> 2;         // 0..63
    const int lc4 = tid & 3;          // float4 index within 16-col row
    const int lg   = lc4 >> 1;        // k-group 0/1
    const int llsb = lc4 & 1;         // position parity within group
    const int wbase = lg * 8 + llsb;  // word base within row

    float acc[4][4][4];
    #pragma unroll
    for (int mt = 0; mt < 4; mt++)
        #pragma unroll
        for (int nt = 0; nt < 4; nt++)
            #pragma unroll
            for (int c = 0; c < 4; c++) acc[mt][nt][c] = 0.f;

    for (int k0 = 0; k0 < K; k0 += 16) {
        #pragma unroll
        for (int half = 0; half < 2; half++) {
            const int r = lr + half * 64;
            float4 av = *(const float4*)&A [(size_t)(m0 + r) * K + k0 + lc4 * 4];
            uint32_t* da = &As[r * AS_STRIDE + wbase];
            da[0] = f2tf32(av.x);
            da[2] = f2tf32(av.y);
            da[4] = f2tf32(av.z);
            da[6] = f2tf32(av.w);
            float4 bv = *(const float4*)&Bt[(size_t)(n0 + r) * K + k0 + lc4 * 4];
            uint32_t* db = &Bs[r * AS_STRIDE + wbase];
            db[0] = f2tf32(bv.x);
            db[2] = f2tf32(bv.y);
            db[4] = f2tf32(bv.z);
            db[6] = f2tf32(bv.w);
        }
        __syncthreads();

        #pragma unroll
        for (int ks = 0; ks < 2; ks++) {
            uint32_t bf[4][2];
            #pragma unroll
            for (int nt = 0; nt < 4; nt++) {
                uint2 v = *(const uint2*)&Bs[(warpN + nt * 8 + gid) * AS_STRIDE + ks * 8 + 2 * tig];
                bf[nt][0] = v.x;   // b0: (k=tig,   n=gid)
                bf[nt][1] = v.y;   // b1: (k=tig+4, n=gid)
            }
            #pragma unroll
            for (int mt = 0; mt < 4; mt++) {
                uint32_t af[4];
                uint2 lo = *(const uint2*)&As[(warpM + mt * 16 +     gid) * AS_STRIDE + ks * 8 + 2 * tig];
                uint2 hi = *(const uint2*)&As[(warpM + mt * 16 + 8 + gid) * AS_STRIDE + ks * 8 + 2 * tig];
                af[0] = lo.x;      // (m=gid,   k=tig)
                af[1] = hi.x;      // (m=gid+8, k=tig)
                af[2] = lo.y;      // (m=gid,   k=tig+4)
                af[3] = hi.y;      // (m=gid+8, k=tig+4)
                #pragma unroll
                for (int nt = 0; nt < 4; nt++)
                    mma_tf32(acc[mt][nt], af, bf[nt]);
            }
        }
        __syncthreads();
    }

    // epilogue: c0,c1 at (m=gid, n=2*tig, 2*tig+1); c2,c3 at m+8
    #pragma unroll
    for (int nt = 0; nt < 4; nt++) {
        const int n = n0 + warpN + nt * 8 + 2 * tig;
        const float b0 = bias[n], b1 = bias[n + 1];
        #pragma unroll
        for (int mt = 0; mt < 4; mt++) {
            const int m = m0 + warpM + mt * 16 + gid;
            float2 v0 = make_float2(acc[mt][nt][0] + b0, acc[mt][nt][1] + b1);
            float2 v1 = make_float2(acc[mt][nt][2] + b0, acc[mt][nt][3] + b1);
            if (relu) {
                v0.x = fmaxf(v0.x, 0.f); v0.y = fmaxf(v0.y, 0.f);
                v1.x = fmaxf(v1.x, 0.f); v1.y = fmaxf(v1.y, 0.f);
            }
            *(float2*)&C[(size_t)m * N + n]       = v0;
            *(float2*)&C[(size_t)(m + 8) * N + n] = v1;
        }
    }
}

// ---------------------------------------------------------------------------
// Flash attention (fp32), single pass with 8-key chunks.
// Grid: (L/128, H, NB). Block: 128 threads. Thread = one q-row.
// ---------------------------------------------------------------------------
__global__ __launch_bounds__(128)
void attn_kernel()
{
    const int n  = blockIdx.z;
    const int h  = blockIdx.y;
    const int q0 = blockIdx.x * 128;
    const int tid = threadIdx.x;
    const int row = n * LQ + q0 + tid;

    __shared__ float Ks[64][64];
    __shared__ float Vs[64][64];

    const float scale = 0.125f;
    float qreg[HD];
    {
        const float* qp = &g_qkv[(size_t)row * (3 * D) + h * HD];
        #pragma unroll
        for (int d = 0; d < HD; d++) qreg[d] = qp[d] * scale;
    }

    float m = -1e30f, l = 0.f;
    float acc[HD];
    #pragma unroll
    for (int d = 0; d < HD; d++) acc[d] = 0.f;

    for (int kt = 0; kt < LQ / 64; kt++) {
        for (int i = tid; i < 64 * 16; i += 128) {
            int r  = i >> 4;
            int c4 = (i & 15) * 4;
            size_t base = (size_t)(n * LQ + kt * 64 + r) * (3 * D) + h * HD + c4;
            *(float4*)&Ks[r][c4] = *(const float4*)&g_qkv[base + D];
            *(float4*)&Vs[r][c4] = *(const float4*)&g_qkv[base + 2 * D];
        }
        __syncthreads();

        #pragma unroll 1
        for (int ch = 0; ch < 8; ch++) {
            float s[8];
            #pragma unroll
            for (int j = 0; j < 8; j++) {
                float t = 0.f;
                #pragma unroll
                for (int d = 0; d < HD; d++) t += qreg[d] * Ks[ch * 8 + j][d];
                s[j] = t;
            }
            float cm = s[0];
            #pragma unroll
            for (int j = 1; j < 8; j++) cm = fmaxf(cm, s[j]);
            if (cm > m) {
                const float corr = __expf(m - cm);
                l *= corr;
                #pragma unroll
                for (int d = 0; d < HD; d++) acc[d] *= corr;
                m = cm;
            }
            #pragma unroll
            for (int j = 0; j < 8; j++) {
                const float p = __expf(s[j] - m);
                l += p;
                #pragma unroll
                for (int d = 0; d < HD; d++) acc[d] += p * Vs[ch * 8 + j][d];
            }
        }
        __syncthreads();
    }

    const float inv = 1.f / l;
    float* op = &g_attn[(size_t)row * D + h * HD];
    #pragma unroll
    for (int d = 0; d < HD; d++) op[d] = acc[d] * inv;
}

// ---------------------------------------------------------------------------
// Residual add + LayerNorm
// ---------------------------------------------------------------------------
__global__ __launch_bounds__(256)
void add_ln_kernel(const float* __restrict__ aext, int aid,
                   const float* __restrict__ bext, int bid,
                   const float* __restrict__ gamma,
                   const float* __restrict__ beta,
                   float* __restrict__ outext, int outid)
{
    const float* a = aext ? aext : scratch(aid);
    const float* b = bext ? bext : scratch(bid);
    float*       o = outext ? outext : scratch(outid);

    const int row = blockIdx.x;
    const int tid = threadIdx.x;
    const size_t base = (size_t)row * D;

    float v[4];
    float s = 0.f, s2 = 0.f;
    #pragma unroll
    for (int i = 0; i < 4; i++) {
        int col = tid + i * 256;
        float x = a[base + col] + b[base + col];
        v[i] = x;
        s  += x;
        s2 += x * x;
    }
    #pragma unroll
    for (int off = 16; off; off >>= 1) {
        s  += __shfl_xor_sync(0xFFFFFFFFu, s,  off);
        s2 += __shfl_xor_sync(0xFFFFFFFFu, s2, off);
    }
    __shared__ float rs[8], rs2[8];
    const int warp = tid >> 5, lane = tid & 31;
    if (lane == 0) { rs[warp] = s; rs2[warp] = s2; }
    __syncthreads();
    float ts = 0.f, ts2 = 0.f;
    #pragma unroll
    for (int w = 0; w < 8; w++) { ts += rs[w]; ts2 += rs2[w]; }

    const float mu  = ts * (1.f / D);
    const float var = ts2 * (1.f / D) - mu * mu;
    const float inv = rsqrtf(var + EPS);

    #pragma unroll
    for (int i = 0; i < 4; i++) {
        int col = tid + i * 256;
        o[base + col] = (v[i] - mu) * inv * gamma[col] + beta[col];
    }
}

// ---------------------------------------------------------------------------
// Launch
// ---------------------------------------------------------------------------
extern "C" void kernel_launch(void* const* d_in, const int* in_sizes, int n_in,
                              void* d_out, int out_size)
{
    const float* x     = (const float*)d_in[0];
    const float* w_qkv = (const float*)d_in[1];
    const float* b_qkv = (const float*)d_in[2];
    const float* w_o   = (const float*)d_in[3];
    const float* b_o   = (const float*)d_in[4];
    const float* g1    = (const float*)d_in[5];
    const float* be1   = (const float*)d_in[6];
    const float* w1    = (const float*)d_in[7];
    const float* b1    = (const float*)d_in[8];
    const float* w2    = (const float*)d_in[9];
    const float* b2    = (const float*)d_in[10];
    const float* g2    = (const float*)d_in[11];
    const float* be2   = (const float*)d_in[12];
    float* out = (float*)d_out;

    // Transpose weights -> [N,K] K-major operands
    transpose_k<<<dim3(3 * D / 32, D / 32), 256>>>(w_qkv, 6, D, 3 * D);
    transpose_k<<<dim3(D / 32,     D / 32), 256>>>(w_o,   7, D, D);
    transpose_k<<<dim3(FF / 32,    D / 32), 256>>>(w1,    8, D, FF);
    transpose_k<<<dim3(D / 32,    FF / 32), 256>>>(w2,    9, FF, D);

    // 1. QKV
    gemm_tf32<<<dim3(3 * D / 128, MROWS / 128), 256>>>(
        x, -1, 6, b_qkv, nullptr, 0, MROWS, 3 * D, D, 0);

    // 2. attention
    attn_kernel<<<dim3(LQ / 128, H_, NB), 128>>>();

    // 3. proj
    gemm_tf32<<<dim3(D / 128, MROWS / 128), 256>>>(
        nullptr, 1, 7, b_o, nullptr, 2, MROWS, D, D, 0);

    // 4. h = LN(proj + x)
    add_ln_kernel<<<MROWS, 256>>>(nullptr, 2, x, -1, g1, be1, nullptr, 3);

    // 5. FF1 (+ReLU)
    gemm_tf32<<<dim3(FF / 128, MROWS / 128), 256>>>(
        nullptr, 3, 8, b1, nullptr, 4, MROWS, FF, D, 1);

    // 6. FF2
    gemm_tf32<<<dim3(D / 128, MROWS / 128), 256>>>(
        nullptr, 4, 9, b2, nullptr, 5, MROWS, D, FF, 0);

    // 7. out = LN(h + ff2)
    add_ln_kernel<<<MROWS, 256>>>(nullptr, 3, nullptr, 5, g2, be2, out, -1);
}

// round 4
// speedup vs baseline: 3.0313x; 1.6527x over previous
#include <cuda_runtime.h>
#include <math.h>
#include <stdint.h>

// Problem constants
#define D     1024
#define H_    16
#define HD    64
#define FF    4096
#define NB    2
#define LQ    2048
#define MROWS (NB * LQ)   // 4096
#define EPS   1e-5f

// ---------------------------------------------------------------------------
// Scratch (device globals — no allocation allowed)
// ---------------------------------------------------------------------------
__device__ float g_qkv  [MROWS * 3 * D];
__device__ float g_attn [MROWS * D];
__device__ float g_proj [MROWS * D];
__device__ float g_h    [MROWS * D];
__device__ float g_ff1  [MROWS * FF];
__device__ float g_ff2  [MROWS * D];
__device__ float g_wqkvT[3 * D * D];
__device__ float g_woT  [D * D];
__device__ float g_w1T  [FF * D];
__device__ float g_w2T  [D * FF];

__device__ __forceinline__ float* scratch(int id) {
    switch (id) {
        case 0:  return g_qkv;
        case 1:  return g_attn;
        case 2:  return g_proj;
        case 3:  return g_h;
        case 4:  return g_ff1;
        case 5:  return g_ff2;
        case 6:  return g_wqkvT;
        case 7:  return g_woT;
        case 8:  return g_w1T;
        default: return g_w2T;
    }
}

// ---------------------------------------------------------------------------
// tf32 helpers (mma.sync path — base sm_103 target OK)
// ---------------------------------------------------------------------------
__device__ __forceinline__ uint32_t f2tf32(float x) {
    uint32_t r;
    asm("cvt.rna.tf32.f32 %0, %1;" : "=r"(r) : "f"(x));
    return r;
}

__device__ __forceinline__ void mma_tf32(float* c, const uint32_t* a, const uint32_t* b) {
    asm volatile(
        "mma.sync.aligned.m16n8k8.row.col.f32.tf32.tf32.f32 "
        "{%0,%1,%2,%3}, {%4,%5,%6,%7}, {%8,%9}, {%0,%1,%2,%3};"
        : "+f"(c[0]), "+f"(c[1]), "+f"(c[2]), "+f"(c[3])
        : "r"(a[0]), "r"(a[1]), "r"(a[2]), "r"(a[3]),
          "r"(b[0]), "r"(b[1]));
}

// ---------------------------------------------------------------------------
// Weight transpose: dst[c][r] = src[r][c]
// ---------------------------------------------------------------------------
__global__ __launch_bounds__(256)
void transpose_k(const float* __restrict__ src, int dstId, int R, int C)
{
    __shared__ float t[32][33];
    float* dst = scratch(dstId);
    const int bx = blockIdx.x * 32;
    const int by = blockIdx.y * 32;
    const int tx = threadIdx.x & 31;
    const int ty = threadIdx.x >> 5;
    #pragma unroll
    for (int i = 0; i < 32; i += 8)
        t[ty + i][tx] = src[(size_t)(by + ty + i) * C + bx + tx];
    __syncthreads();
    #pragma unroll
    for (int i = 0; i < 32; i += 8)
        dst[(size_t)(bx + ty + i) * R + by + tx] = t[tx][ty + i];
}

// ---------------------------------------------------------------------------
// TF32 tensor-core GEMM (unchanged from R3)
// ---------------------------------------------------------------------------
#define AS_STRIDE 24

__global__ __launch_bounds__(256)
void gemm_tf32(const float* __restrict__ Aext, int Aid, int Bid,
               const float* __restrict__ bias,
               float* __restrict__ Cext, int Cid,
               int M, int N, int K, int relu)
{
    __shared__ uint32_t As[128 * AS_STRIDE];
    __shared__ uint32_t Bs[128 * AS_STRIDE];

    const float* A  = Aext ? Aext : scratch(Aid);
    const float* Bt = scratch(Bid);
    float*       C  = Cext ? Cext : scratch(Cid);

    const int tid   = threadIdx.x;
    const int wid   = tid >> 5;
    const int lane  = tid & 31;
    const int gid   = lane >> 2;
    const int tig   = lane & 3;
    const int warpM = (wid & 1) * 64;
    const int warpN = (wid >> 1) * 32;
    const int m0    = blockIdx.y * 128;
    const int n0    = blockIdx.x * 128;

    const int lr  = tid >> 2;
    const int lc4 = tid & 3;
    const int wbase = (lc4 >> 1) * 8 + (lc4 & 1);

    float acc[4][4][4];
    #pragma unroll
    for (int mt = 0; mt < 4; mt++)
        #pragma unroll
        for (int nt = 0; nt < 4; nt++)
            #pragma unroll
            for (int c = 0; c < 4; c++) acc[mt][nt][c] = 0.f;

    for (int k0 = 0; k0 < K; k0 += 16) {
        #pragma unroll
        for (int half = 0; half < 2; half++) {
            const int r = lr + half * 64;
            float4 av = *(const float4*)&A [(size_t)(m0 + r) * K + k0 + lc4 * 4];
            uint32_t* da = &As[r * AS_STRIDE + wbase];
            da[0] = f2tf32(av.x); da[2] = f2tf32(av.y);
            da[4] = f2tf32(av.z); da[6] = f2tf32(av.w);
            float4 bv = *(const float4*)&Bt[(size_t)(n0 + r) * K + k0 + lc4 * 4];
            uint32_t* db = &Bs[r * AS_STRIDE + wbase];
            db[0] = f2tf32(bv.x); db[2] = f2tf32(bv.y);
            db[4] = f2tf32(bv.z); db[6] = f2tf32(bv.w);
        }
        __syncthreads();

        #pragma unroll
        for (int ks = 0; ks < 2; ks++) {
            uint32_t bf[4][2];
            #pragma unroll
            for (int nt = 0; nt < 4; nt++) {
                uint2 v = *(const uint2*)&Bs[(warpN + nt * 8 + gid) * AS_STRIDE + ks * 8 + 2 * tig];
                bf[nt][0] = v.x;
                bf[nt][1] = v.y;
            }
            #pragma unroll
            for (int mt = 0; mt < 4; mt++) {
                uint32_t af[4];
                uint2 lo = *(const uint2*)&As[(warpM + mt * 16 +     gid) * AS_STRIDE + ks * 8 + 2 * tig];
                uint2 hi = *(const uint2*)&As[(warpM + mt * 16 + 8 + gid) * AS_STRIDE + ks * 8 + 2 * tig];
                af[0] = lo.x; af[1] = hi.x; af[2] = lo.y; af[3] = hi.y;
                #pragma unroll
                for (int nt = 0; nt < 4; nt++)
                    mma_tf32(acc[mt][nt], af, bf[nt]);
            }
        }
        __syncthreads();
    }

    #pragma unroll
    for (int nt = 0; nt < 4; nt++) {
        const int n = n0 + warpN + nt * 8 + 2 * tig;
        const float b0 = bias[n], b1 = bias[n + 1];
        #pragma unroll
        for (int mt = 0; mt < 4; mt++) {
            const int m = m0 + warpM + mt * 16 + gid;
            float2 v0 = make_float2(acc[mt][nt][0] + b0, acc[mt][nt][1] + b1);
            float2 v1 = make_float2(acc[mt][nt][2] + b0, acc[mt][nt][3] + b1);
            if (relu) {
                v0.x = fmaxf(v0.x, 0.f); v0.y = fmaxf(v0.y, 0.f);
                v1.x = fmaxf(v1.x, 0.f); v1.y = fmaxf(v1.y, 0.f);
            }
            *(float2*)&C[(size_t)m * N + n]       = v0;
            *(float2*)&C[(size_t)(m + 8) * N + n] = v1;
        }
    }
}

// ---------------------------------------------------------------------------
// Tensor-core flash attention (tf32 mma.sync).
// Block: 128 threads (4 warps), 128 q-rows; key tiles of 64.
// Q a-frags in registers (scale*log2e folded), K smem K-major (stride 72),
// V smem transposed [d][key] (stride 74). P accum->A-frag via quad shuffles.
// ---------------------------------------------------------------------------
#define KS_STRIDE 72
#define VS_STRIDE 74

__global__ __launch_bounds__(128)
void attn_mma()
{
    __shared__ uint32_t sm[64 * KS_STRIDE + 64 * VS_STRIDE];  // 9344 words; Q stage uses first 9216

    const int nB  = blockIdx.z;
    const int h   = blockIdx.y;
    const int q0  = blockIdx.x * 128;
    const int tid = threadIdx.x;
    const int wid = tid >> 5;
    const int lane = tid & 31;
    const int gid  = lane >> 2;
    const int tig  = lane & 3;
    const int warpM = wid * 32;
    const float qscale = 0.125f * 1.44269504f;   // 1/sqrt(64) * log2(e)

    // ---- stage Q into smem (permuted), extract a-frags, then free smem ----
    #pragma unroll
    for (int t = 0; t < 16; t++) {
        const int i  = tid + t * 128;
        const int r  = i >> 4;
        const int c4 = i & 15;
        const float4 v = *(const float4*)&g_qkv[(size_t)(nB * LQ + q0 + r) * (3 * D) + h * HD + c4 * 4];
        uint32_t* dst = &sm[r * KS_STRIDE + (c4 >> 2) * 16 + ((c4 & 3) >> 1) * 8 + (c4 & 1)];
        dst[0] = f2tf32(v.x * qscale); dst[2] = f2tf32(v.y * qscale);
        dst[4] = f2tf32(v.z * qscale); dst[6] = f2tf32(v.w * qscale);
    }
    __syncthreads();

    uint32_t qf[2][8][4];
    #pragma unroll
    for (int mt = 0; mt < 2; mt++) {
        const int rlo = warpM + mt * 16 + gid;
        #pragma unroll
        for (int ks = 0; ks < 8; ks++) {
            uint2 lo = *(const uint2*)&sm[ rlo      * KS_STRIDE + (ks >> 1) * 16 + (ks & 1) * 8 + 2 * tig];
            uint2 hi = *(const uint2*)&sm[(rlo + 8) * KS_STRIDE + (ks >> 1) * 16 + (ks & 1) * 8 + 2 * tig];
            qf[mt][ks][0] = lo.x; qf[mt][ks][1] = hi.x;
            qf[mt][ks][2] = lo.y; qf[mt][ks][3] = hi.y;
        }
    }
    __syncthreads();

    uint32_t* Ks = sm;
    uint32_t* Vs = sm + 64 * KS_STRIDE;

    float oac[2][8][4];
    #pragma unroll
    for (int mt = 0; mt < 2; mt++)
        #pragma unroll
        for (int nt = 0; nt < 8; nt++)
            #pragma unroll
            for (int c = 0; c < 4; c++) oac[mt][nt][c] = 0.f;
    float mrow[2][2] = {{-1e30f, -1e30f}, {-1e30f, -1e30f}};
    float lrow[2][2] = {{0.f, 0.f}, {0.f, 0.f}};

    for (int kt = 0; kt < LQ / 64; kt++) {
        // K tile: rows = key, cols = d (tf32, permuted)
        #pragma unroll
        for (int t = 0; t < 8; t++) {
            const int i  = tid + t * 128;
            const int r  = i >> 4;
            const int c4 = i & 15;
            const size_t base = (size_t)(nB * LQ + kt * 64 + r) * (3 * D) + h * HD + c4 * 4;
            const float4 v = *(const float4*)&g_qkv[base + D];
            uint32_t* dst = &Ks[r * KS_STRIDE + (c4 >> 2) * 16 + ((c4 & 3) >> 1) * 8 + (c4 & 1)];
            dst[0] = f2tf32(v.x); dst[2] = f2tf32(v.y);
            dst[4] = f2tf32(v.z); dst[6] = f2tf32(v.w);
        }
        // V tile transposed: rows = d, cols = key (permuted along key)
        #pragma unroll
        for (int t = 0; t < 8; t++) {
            const int i   = tid + t * 128;
            const int key = i >> 4;
            const int c4  = i & 15;
            const size_t base = (size_t)(nB * LQ + kt * 64 + key) * (3 * D) + h * HD + c4 * 4;
            const float4 v = *(const float4*)&g_qkv[base + 2 * D];
            const int kpos = (key >> 4) * 16 + ((key & 3) << 1) + ((key >> 2) & 1) + (key & 8);
            const int d0 = c4 * 4;
            Vs[(d0 + 0) * VS_STRIDE + kpos] = f2tf32(v.x);
            Vs[(d0 + 1) * VS_STRIDE + kpos] = f2tf32(v.y);
            Vs[(d0 + 2) * VS_STRIDE + kpos] = f2tf32(v.z);
            Vs[(d0 + 3) * VS_STRIDE + kpos] = f2tf32(v.w);
        }
        __syncthreads();

        // ---- S = Q @ K^T (scaled, log2 domain) ----
        float sacc[2][8][4];
        #pragma unroll
        for (int mt = 0; mt < 2; mt++)
            #pragma unroll
            for (int nt = 0; nt < 8; nt++)
                #pragma unroll
                for (int c = 0; c < 4; c++) sacc[mt][nt][c] = 0.f;

        #pragma unroll
        for (int ks = 0; ks < 8; ks++) {
            #pragma unroll
            for (int nt = 0; nt < 8; nt++) {
                uint2 bv = *(const uint2*)&Ks[(nt * 8 + gid) * KS_STRIDE + (ks >> 1) * 16 + (ks & 1) * 8 + 2 * tig];
                uint32_t bf[2] = {bv.x, bv.y};
                mma_tf32(sacc[0][nt], qf[0][ks], bf);
                mma_tf32(sacc[1][nt], qf[1][ks], bf);
            }
        }

        // ---- online softmax on fragments ----
        #pragma unroll
        for (int mt = 0; mt < 2; mt++) {
            float mx0 = -1e30f, mx1 = -1e30f;
            #pragma unroll
            for (int nt = 0; nt < 8; nt++) {
                mx0 = fmaxf(mx0, fmaxf(sacc[mt][nt][0], sacc[mt][nt][1]));
                mx1 = fmaxf(mx1, fmaxf(sacc[mt][nt][2], sacc[mt][nt][3]));
            }
            mx0 = fmaxf(mx0, __shfl_xor_sync(0xFFFFFFFFu, mx0, 1));
            mx0 = fmaxf(mx0, __shfl_xor_sync(0xFFFFFFFFu, mx0, 2));
            mx1 = fmaxf(mx1, __shfl_xor_sync(0xFFFFFFFFu, mx1, 1));
            mx1 = fmaxf(mx1, __shfl_xor_sync(0xFFFFFFFFu, mx1, 2));

            const float mn0 = fmaxf(mrow[mt][0], mx0);
            const float mn1 = fmaxf(mrow[mt][1], mx1);
            const float cr0 = exp2f(mrow[mt][0] - mn0);
            const float cr1 = exp2f(mrow[mt][1] - mn1);
            mrow[mt][0] = mn0;
            mrow[mt][1] = mn1;

            float ls0 = 0.f, ls1 = 0.f;
            #pragma unroll
            for (int nt = 0; nt < 8; nt++) {
                sacc[mt][nt][0] = exp2f(sacc[mt][nt][0] - mn0);
                sacc[mt][nt][1] = exp2f(sacc[mt][nt][1] - mn0);
                sacc[mt][nt][2] = exp2f(sacc[mt][nt][2] - mn1);
                sacc[mt][nt][3] = exp2f(sacc[mt][nt][3] - mn1);
                ls0 += sacc[mt][nt][0] + sacc[mt][nt][1];
                ls1 += sacc[mt][nt][2] + sacc[mt][nt][3];
            }
            ls0 += __shfl_xor_sync(0xFFFFFFFFu, ls0, 1);
            ls0 += __shfl_xor_sync(0xFFFFFFFFu, ls0, 2);
            ls1 += __shfl_xor_sync(0xFFFFFFFFu, ls1, 1);
            ls1 += __shfl_xor_sync(0xFFFFFFFFu, ls1, 2);
            lrow[mt][0] = lrow[mt][0] * cr0 + ls0;
            lrow[mt][1] = lrow[mt][1] * cr1 + ls1;

            #pragma unroll
            for (int nt = 0; nt < 8; nt++) {
                oac[mt][nt][0] *= cr0; oac[mt][nt][1] *= cr0;
                oac[mt][nt][2] *= cr1; oac[mt][nt][3] *= cr1;
            }
        }

        // ---- O += P @ V ----
        const int s1 = (lane & ~3) | (tig >> 1);
        const int s2 = s1 + 2;
        const bool odd = (tig & 1) != 0;
        #pragma unroll
        for (int kk = 0; kk < 8; kk++) {
            uint32_t pa[2][4];
            #pragma unroll
            for (int mt = 0; mt < 2; mt++) {
                const float c0 = sacc[mt][kk][0], c1 = sacc[mt][kk][1];
                const float c2 = sacc[mt][kk][2], c3 = sacc[mt][kk][3];
                const float x0 = __shfl_sync(0xFFFFFFFFu, c0, s1);
                const float x1 = __shfl_sync(0xFFFFFFFFu, c1, s1);
                const float x2 = __shfl_sync(0xFFFFFFFFu, c2, s1);
                const float x3 = __shfl_sync(0xFFFFFFFFu, c3, s1);
                const float y0 = __shfl_sync(0xFFFFFFFFu, c0, s2);
                const float y1 = __shfl_sync(0xFFFFFFFFu, c1, s2);
                const float y2 = __shfl_sync(0xFFFFFFFFu, c2, s2);
                const float y3 = __shfl_sync(0xFFFFFFFFu, c3, s2);
                pa[mt][0] = f2tf32(odd ? x1 : x0);
                pa[mt][1] = f2tf32(odd ? x3 : x2);
                pa[mt][2] = f2tf32(odd ? y1 : y0);
                pa[mt][3] = f2tf32(odd ? y3 : y2);
            }
            #pragma unroll
            for (int ntd = 0; ntd < 8; ntd++) {
                uint2 bv = *(const uint2*)&Vs[(ntd * 8 + gid) * VS_STRIDE + (kk >> 1) * 16 + (kk & 1) * 8 + 2 * tig];
                uint32_t bf[2] = {bv.x, bv.y};
                mma_tf32(oac[0][ntd], pa[0], bf);
                mma_tf32(oac[1][ntd], pa[1], bf);
            }
        }
        __syncthreads();
    }

    // ---- normalize + store ----
    #pragma unroll
    for (int mt = 0; mt < 2; mt++) {
        const float inv0 = 1.f / lrow[mt][0];
        const float inv1 = 1.f / lrow[mt][1];
        const int grow = nB * LQ + q0 + warpM + mt * 16 + gid;
        #pragma unroll
        for (int ntd = 0; ntd < 8; ntd++) {
            const int col = h * HD + ntd * 8 + 2 * tig;
            *(float2*)&g_attn[(size_t)grow * D + col] =
                make_float2(oac[mt][ntd][0] * inv0, oac[mt][ntd][1] * inv0);
            *(float2*)&g_attn[(size_t)(grow + 8) * D + col] =
                make_float2(oac[mt][ntd][2] * inv1, oac[mt][ntd][3] * inv1);
        }
    }
}

// ---------------------------------------------------------------------------
// Residual add + LayerNorm
// ---------------------------------------------------------------------------
__global__ __launch_bounds__(256)
void add_ln_kernel(const float* __restrict__ aext, int aid,
                   const float* __restrict__ bext, int bid,
                   const float* __restrict__ gamma,
                   const float* __restrict__ beta,
                   float* __restrict__ outext, int outid)
{
    const float* a = aext ? aext : scratch(aid);
    const float* b = bext ? bext : scratch(bid);
    float*       o = outext ? outext : scratch(outid);

    const int row = blockIdx.x;
    const int tid = threadIdx.x;
    const size_t base = (size_t)row * D;

    float v[4];
    float s = 0.f, s2 = 0.f;
    #pragma unroll
    for (int i = 0; i < 4; i++) {
        int col = tid + i * 256;
        float x = a[base + col] + b[base + col];
        v[i] = x;
        s  += x;
        s2 += x * x;
    }
    #pragma unroll
    for (int off = 16; off; off >>= 1) {
        s  += __shfl_xor_sync(0xFFFFFFFFu, s,  off);
        s2 += __shfl_xor_sync(0xFFFFFFFFu, s2, off);
    }
    __shared__ float rs[8], rs2[8];
    const int warp = tid >> 5, lane = tid & 31;
    if (lane == 0) { rs[warp] = s; rs2[warp] = s2; }
    __syncthreads();
    float ts = 0.f, ts2 = 0.f;
    #pragma unroll
    for (int w = 0; w < 8; w++) { ts += rs[w]; ts2 += rs2[w]; }

    const float mu  = ts * (1.f / D);
    const float var = ts2 * (1.f / D) - mu * mu;
    const float inv = rsqrtf(var + EPS);

    #pragma unroll
    for (int i = 0; i < 4; i++) {
        int col = tid + i * 256;
        o[base + col] = (v[i] - mu) * inv * gamma[col] + beta[col];
    }
}

// ---------------------------------------------------------------------------
// Launch
// ---------------------------------------------------------------------------
extern "C" void kernel_launch(void* const* d_in, const int* in_sizes, int n_in,
                              void* d_out, int out_size)
{
    const float* x     = (const float*)d_in[0];
    const float* w_qkv = (const float*)d_in[1];
    const float* b_qkv = (const float*)d_in[2];
    const float* w_o   = (const float*)d_in[3];
    const float* b_o   = (const float*)d_in[4];
    const float* g1    = (const float*)d_in[5];
    const float* be1   = (const float*)d_in[6];
    const float* w1    = (const float*)d_in[7];
    const float* b1    = (const float*)d_in[8];
    const float* w2    = (const float*)d_in[9];
    const float* b2    = (const float*)d_in[10];
    const float* g2    = (const float*)d_in[11];
    const float* be2   = (const float*)d_in[12];
    float* out = (float*)d_out;

    // Transpose weights -> [N,K] K-major operands
    transpose_k<<<dim3(3 * D / 32, D / 32), 256>>>(w_qkv, 6, D, 3 * D);
    transpose_k<<<dim3(D / 32,     D / 32), 256>>>(w_o,   7, D, D);
    transpose_k<<<dim3(FF / 32,    D / 32), 256>>>(w1,    8, D, FF);
    transpose_k<<<dim3(D / 32,    FF / 32), 256>>>(w2,    9, FF, D);

    // 1. QKV
    gemm_tf32<<<dim3(3 * D / 128, MROWS / 128), 256>>>(
        x, -1, 6, b_qkv, nullptr, 0, MROWS, 3 * D, D, 0);

    // 2. attention (tensor-core flash)
    attn_mma<<<dim3(LQ / 128, H_, NB), 128>>>();

    // 3. proj
    gemm_tf32<<<dim3(D / 128, MROWS / 128), 256>>>(
        nullptr, 1, 7, b_o, nullptr, 2, MROWS, D, D, 0);

    // 4. h = LN(proj + x)
    add_ln_kernel<<<MROWS, 256>>>(nullptr, 2, x, -1, g1, be1, nullptr, 3);

    // 5. FF1 (+ReLU)
    gemm_tf32<<<dim3(FF / 128, MROWS / 128), 256>>>(
        nullptr, 3, 8, b1, nullptr, 4, MROWS, FF, D, 1);

    // 6. FF2
    gemm_tf32<<<dim3(D / 128, MROWS / 128), 256>>>(
        nullptr, 4, 9, b2, nullptr, 5, MROWS, D, FF, 0);

    // 7. out = LN(h + ff2)
    add_ln_kernel<<<MROWS, 256>>>(nullptr, 3, nullptr, 5, g2, be2, out, -1);
}